// round 11
// baseline (speedup 1.0000x reference)
#include <cuda_runtime.h>

#define NPTS   4096
#define DOUT   3
#define IBLK   128
#define JCHUNK 128
#define NIB    (NPTS / IBLK)    // 32
#define NJB    (NPTS / JCHUNK)  // 32

// Partial sums: [jb][i][{num012,_},{den012,_}] — fully overwritten every
// replay (no reset, no atomics on data). 32*4096*32B = 4 MB, L2-resident.
__device__ float4 g_part[NJB * NPTS * 2];
// Per-i-block arrival counters for the last-CTA reduction (reset by reducer).
__device__ int g_cnt[NIB];

__device__ __forceinline__ float ex2f(float x) {
    float y;
    asm("ex2.approx.ftz.f32 %0, %1;" : "=f"(y) : "f"(x));
    return y;
}

// Identical projection code path for query-side (x) and train-side (train_X):
// row i of both produces bitwise-equal {F0,F1,F2}, so the self-pair term
// A_i * ex2(fma(q,2q,-q^2)) == ex2(-q^2)*ex2(q^2*(1-eps)) ~= 1 to ~1e-6;
// finalize subtracts exactly 1.0 (residual negligible vs den ~ O(100)).
__device__ __forceinline__ void proj3(float4 v, const float* __restrict__ w, float s,
                                      float& f0, float& f1, float& f2) {
    f0 = (v.x * w[0] + v.y * w[1] + v.z * w[2]  + v.w * w[3])  * s;
    f1 = (v.x * w[4] + v.y * w[5] + v.z * w[6]  + v.w * w[7])  * s;
    f2 = (v.x * w[8] + v.y * w[9] + v.z * w[10] + v.w * w[11]) * s;
}

__global__ void __launch_bounds__(IBLK) fused_kernel(const float* __restrict__ x,
                                                     const float* __restrict__ tx,
                                                     const float* __restrict__ Y,
                                                     const float* __restrict__ W,
                                                     const float* __restrict__ h,
                                                     float* __restrict__ out) {
    // sh[3j+0]={P0,P1,P2,_}  sh[3j+1]={Q0,Q1,Q2,_}  sh[3j+2]={Y0,Y1,Y2,_}
    __shared__ float4 sh[3 * JCHUNK];  // 6 KB
    __shared__ int s_last;

    int tid = threadIdx.x;
    int bx  = blockIdx.x;
    int i   = bx * IBLK + tid;
    int j0  = blockIdx.y * JCHUNK;

    // b = sqrt(0.5*log2(e))/h :  exp(-0.5*((a-c)/h)^2) = ex2(-(b(a-c))^2)
    float b = 0.8493218002880191f / __ldg(h);

    float w[12];
#pragma unroll
    for (int k = 0; k < 12; k++) w[k] = __ldg(&W[k]);

    // Stage this CTA's j-chunk: P = 2t, Q = -t^2 per channel, plus Y.
    {
        int j = j0 + tid;  // JCHUNK == IBLK
        float4 tv = reinterpret_cast<const float4*>(tx)[j];
        float t0, t1, t2;
        proj3(tv, w, b, t0, t1, t2);
        sh[3 * tid + 0] = make_float4(t0 + t0, t1 + t1, t2 + t2, 0.0f);
        sh[3 * tid + 1] = make_float4(-t0 * t0, -t1 * t1, -t2 * t2, 0.0f);
        sh[3 * tid + 2] = make_float4(__ldg(&Y[j * 3 + 0]),
                                      __ldg(&Y[j * 3 + 1]),
                                      __ldg(&Y[j * 3 + 2]), 0.0f);
    }

    // This thread's query projection (identical code path as train side).
    float4 xv = reinterpret_cast<const float4*>(x)[i];
    float q0, q1, q2;
    proj3(xv, w, b, q0, q1, q2);
    // A_c = ex2(-q_c^2): common factor of num and den for this (i, channel).
    float a0 = ex2f(-q0 * q0), a1 = ex2f(-q1 * q1), a2 = ex2f(-q2 * q2);

    float n0 = 0.f, n1 = 0.f, n2 = 0.f;
    float d0 = 0.f, d1 = 0.f, d2 = 0.f;

    __syncthreads();

    // Per (j, channel): FFMA(arg) + EX2 + FADD(den) + FFMA(num).
    // FMA pipe 9 ops (18 SMSP-cyc) < MUFU 3 ops (24 SMSP-cyc) -> MUFU-bound.
#pragma unroll 8
    for (int j = 0; j < JCHUNK; j++) {
        float4 P  = sh[3 * j + 0];  // broadcast LDS.128
        float4 Q  = sh[3 * j + 1];
        float4 yv = sh[3 * j + 2];
        float e0 = ex2f(fmaf(q0, P.x, Q.x));
        float e1 = ex2f(fmaf(q1, P.y, Q.y));
        float e2 = ex2f(fmaf(q2, P.z, Q.z));
        d0 += e0;  n0 = fmaf(e0, yv.x, n0);
        d1 += e1;  n1 = fmaf(e1, yv.y, n1);
        d2 += e2;  n2 = fmaf(e2, yv.z, n2);
    }

    // Scale by A_i so partials are in true-K units.
    int base = (blockIdx.y * NPTS + i) * 2;
    g_part[base]     = make_float4(n0 * a0, n1 * a1, n2 * a2, 0.0f);
    g_part[base + 1] = make_float4(d0 * a0, d1 * a1, d2 * a2, 0.0f);

    // Last-arriving CTA of this i-block reduces all NJB partials.
    if (tid == 0) {
        __threadfence();
        int old = atomicAdd(&g_cnt[bx], 1);
        s_last = (old == NJB - 1);
        if (s_last) g_cnt[bx] = 0;  // reset for next graph replay
    }
    __syncthreads();

    if (s_last) {
        __threadfence();  // make other CTAs' partials visible
        float rn0 = 0.f, rn1 = 0.f, rn2 = 0.f;
        float rd0 = 0.f, rd1 = 0.f, rd2 = 0.f;
#pragma unroll
        for (int jb = 0; jb < NJB; jb++) {
            int p = (jb * NPTS + i) * 2;
            float4 aa = g_part[p];
            float4 bb = g_part[p + 1];
            rn0 += aa.x;  rn1 += aa.y;  rn2 += aa.z;
            rd0 += bb.x;  rd1 += bb.y;  rd2 += bb.z;
        }
        // Remove self-pair contribution (== 1.0 to ~1e-6).
        float y0 = __ldg(&Y[i * 3 + 0]);
        float y1 = __ldg(&Y[i * 3 + 1]);
        float y2 = __ldg(&Y[i * 3 + 2]);
        out[i * 3 + 0] = (rn0 - y0) / (rd0 - 1.0f);
        out[i * 3 + 1] = (rn1 - y1) / (rd1 - 1.0f);
        out[i * 3 + 2] = (rn2 - y2) / (rd2 - 1.0f);
    }
}

extern "C" void kernel_launch(void* const* d_in, const int* in_sizes, int n_in,
                              void* d_out, int out_size) {
    const float* x  = (const float*)d_in[0];
    const float* tx = (const float*)d_in[1];
    const float* Y  = (const float*)d_in[2];
    const float* W  = (const float*)d_in[3];
    const float* h  = (const float*)d_in[4];
    float* out = (float*)d_out;

    fused_kernel<<<dim3(NIB, NJB), IBLK>>>(x, tx, Y, W, h, out);
}

// round 13
// speedup vs baseline: 1.2926x; 1.2926x over previous
#include <cuda_runtime.h>

#define NPTS   4096
#define DOUT   3
#define IBLK   128
#define JCHUNK 128
#define NIB    (NPTS / IBLK)    // 32
#define NJB    (NPTS / JCHUNK)  // 32

// Partial sums: [jb][i][{num012,_},{den012,_}] — fully overwritten every
// replay (no reset, no atomics). 32*4096*32B = 4 MB, L2-resident.
__device__ float4 g_part[NJB * NPTS * 2];

typedef unsigned long long u64;

__device__ __forceinline__ float ex2neg(float m) {
    // ptxas folds the PTX neg into the MUFU operand modifier.
    float y;
    asm("ex2.approx.ftz.f32 %0, %1;" : "=f"(y) : "f"(-m));
    return y;
}
__device__ __forceinline__ u64 pk2(float lo, float hi) {
    u64 r; asm("mov.b64 %0, {%1, %2};" : "=l"(r) : "f"(lo), "f"(hi)); return r;
}
__device__ __forceinline__ void upk2(u64 v, float& lo, float& hi) {
    asm("mov.b64 {%0, %1}, %2;" : "=f"(lo), "=f"(hi) : "l"(v));
}
__device__ __forceinline__ u64 add2(u64 a, u64 b) {
    u64 r; asm("add.rn.f32x2 %0, %1, %2;" : "=l"(r) : "l"(a), "l"(b)); return r;
}
__device__ __forceinline__ u64 mul2(u64 a, u64 b) {
    u64 r; asm("mul.rn.f32x2 %0, %1, %2;" : "=l"(r) : "l"(a), "l"(b)); return r;
}

// Identical projection code path for query-side (x) and train-side (train_X)
// so row i of both is bitwise-equal -> u = F - q == 0 exactly at the self
// pair -> kernel value exactly 1.0, removed exactly in finalize.
__device__ __forceinline__ void proj3(float4 v, const float* __restrict__ w, float s,
                                      float& f0, float& f1, float& f2) {
    f0 = (v.x * w[0] + v.y * w[1] + v.z * w[2]  + v.w * w[3])  * s;
    f1 = (v.x * w[4] + v.y * w[5] + v.z * w[6]  + v.w * w[7])  * s;
    f2 = (v.x * w[8] + v.y * w[9] + v.z * w[10] + v.w * w[11]) * s;
}

__global__ void __launch_bounds__(IBLK) pair_kernel(const float* __restrict__ x,
                                                    const float* __restrict__ tx,
                                                    const float* __restrict__ Y,
                                                    const float* __restrict__ W,
                                                    const float* __restrict__ h) {
    __shared__ float4 sh[2 * JCHUNK];  // 4 KB: per-j {F0,F1,F2,_},{Y0,Y1,Y2,_}

    int tid = threadIdx.x;
    int i   = blockIdx.x * IBLK + tid;
    int j0  = blockIdx.y * JCHUNK;

    // exp(-0.5*((a-c)/h)^2) = ex2(-(b(a-c))^2), b = sqrt(0.5*log2(e))/h
    float b = 0.8493218002880191f / __ldg(h);

    float w[12];
#pragma unroll
    for (int k = 0; k < 12; k++) w[k] = __ldg(&W[k]);

    // Stage this CTA's j-chunk: project train_X rows + fetch Y rows.
    {
        int j = j0 + tid;  // JCHUNK == IBLK
        float4 tv = reinterpret_cast<const float4*>(tx)[j];
        float t0, t1, t2;
        proj3(tv, w, b, t0, t1, t2);
        sh[2 * tid]     = make_float4(t0, t1, t2, 0.0f);
        sh[2 * tid + 1] = make_float4(__ldg(&Y[j * 3 + 0]),
                                      __ldg(&Y[j * 3 + 1]),
                                      __ldg(&Y[j * 3 + 2]), 0.0f);
    }

    // This thread's query projection (identical code path as train side).
    float4 xv = reinterpret_cast<const float4*>(x)[i];
    float q0, q1, q2;
    proj3(xv, w, b, q0, q1, q2);
    u64 nq01 = pk2(-q0, -q1);  // packed negated query, channels 0/1

    float n0 = 0.f, n1 = 0.f, n2 = 0.f;
    float d0 = 0.f, d1 = 0.f, d2 = 0.f;

    __syncthreads();

    // Per j: 2 broadcast LDS.128; FMA pipe = ADD2 + MUL2 + FADD + FMUL
    // + 3 FADD(den) + 3 FFMA(num) = 10 ops (20 cyc) < MUFU 3x8 = 24 cyc
    // -> MUFU is the sole binder.
#pragma unroll 8
    for (int j = 0; j < JCHUNK; j++) {
        float4 f  = sh[2 * j];      // broadcast LDS.128
        float4 yv = sh[2 * j + 1];  // broadcast LDS.128

        u64 F01 = pk2(f.x, f.y);            // aligned pair from LDS.128: free
        u64 u01 = add2(F01, nq01);          // u = F - q (exact 0 at self-pair)
        u64 m01 = mul2(u01, u01);
        float m0, m1;
        upk2(m01, m0, m1);
        float u2 = f.z - q2;
        float m2 = u2 * u2;

        float e0 = ex2neg(m0);
        float e1 = ex2neg(m1);
        float e2 = ex2neg(m2);

        d0 += e0;  n0 = fmaf(e0, yv.x, n0);
        d1 += e1;  n1 = fmaf(e1, yv.y, n1);
        d2 += e2;  n2 = fmaf(e2, yv.z, n2);
    }

    int base = (blockIdx.y * NPTS + i) * 2;
    g_part[base]     = make_float4(n0, n1, n2, 0.0f);
    g_part[base + 1] = make_float4(d0, d1, d2, 0.0f);
}

// One thread per (point, slot): slot s in 0..7 maps to {n0,n1,n2,pad,d0,d1,d2,pad}.
// 32768 threads; each sums 32 jb-partials (independent strided loads, MLP=32).
// A warp's lanes cover 32 consecutive floats -> every load is a coalesced 128B line.
__global__ void __launch_bounds__(256) finalize_kernel(const float* __restrict__ Y,
                                                       float* __restrict__ out) {
    int t = blockIdx.x * 256 + threadIdx.x;   // 0 .. 32767
    int i = t >> 3;
    int s = t & 7;

    const float* p = reinterpret_cast<const float*>(g_part);

    float acc = 0.0f;
#pragma unroll
    for (int jb = 0; jb < NJB; jb++)
        acc += p[(jb * NPTS + i) * 8 + s];

    // Pair numerator (lane t) with denominator (lane t+4, same warp).
    float den = __shfl_down_sync(0xFFFFFFFFu, acc, 4);

    if (s < DOUT) {
        // Remove exact self-pair contribution (K_ii == 1.0 bitwise).
        float y = __ldg(&Y[i * 3 + s]);
        out[i * 3 + s] = (acc - y) / (den - 1.0f);
    }
}

extern "C" void kernel_launch(void* const* d_in, const int* in_sizes, int n_in,
                              void* d_out, int out_size) {
    const float* x  = (const float*)d_in[0];
    const float* tx = (const float*)d_in[1];
    const float* Y  = (const float*)d_in[2];
    const float* W  = (const float*)d_in[3];
    const float* h  = (const float*)d_in[4];
    float* out = (float*)d_out;

    pair_kernel<<<dim3(NIB, NJB), IBLK>>>(x, tx, Y, W, h);
    finalize_kernel<<<NPTS * 8 / 256, 256>>>(Y, out);
}